// round 2
// baseline (speedup 1.0000x reference)
#include <cuda_runtime.h>
#include <math.h>

#define NN 10000
#define NE 160000
#define NB 10
#define RN 100
#define WN 704
#define EB 32
#define SWS 705   /* padded shared stride for w tile */

#define SQ3   1.7320508075688772f
#define ISQ3  0.5773502691896258f
#define SQ75  2.7386127875258306f
#define C_SC  0.25f
#define C_V0  0.35355339059327373f
#define C_CG  0.20412414523193152f   /* 1/sqrt(24) */
#define I24   0.20412414523193152f
#define I32   0.17677669529663687f
#define I8    0.35355339059327373f
#define I16   0.25f
#define THIRD 0.3333333333333333f

__device__ float g_rbf[NE*NB];
__device__ float g_sh1[NE*3];
__device__ float g_s[NN*16];
__device__ float g_v[NN*24];
__device__ float g_aggs[NN*24];
__device__ float g_aggv[NN*96];

// ---------------------------------------------------------------- geometry
__global__ void geom_kernel(const float* __restrict__ pos,
                            const int* __restrict__ row,
                            const int* __restrict__ col) {
    int e = blockIdx.x * 256 + threadIdx.x;
    if (e >= NE) return;
    int r = row[e], c = col[e];
    float vx = pos[3*r+0] - pos[3*c+0];
    float vy = pos[3*r+1] - pos[3*c+1];
    float vz = pos[3*r+2] - pos[3*c+2];
    float len = sqrtf(vx*vx + vy*vy + vz*vz + 1e-12f);
    float inv = 1.0f / len;
    g_sh1[3*e+0] = SQ3 * vx * inv;
    g_sh1[3*e+1] = SQ3 * vy * inv;
    g_sh1[3*e+2] = SQ3 * vz * inv;
    const float step = 10.0f / 9.0f;
#pragma unroll
    for (int k = 0; k < NB; k++) {
        float d = len - (float)k * step;
        g_rbf[e*NB + k] = expf(-0.405f * d * d);   // coeff = -0.5/(10/9)^2 exactly
    }
}

// ---------------------------------------------------------------- init: s = x@embed/sqrt8, zero v/agg
__global__ void init_kernel(const float* __restrict__ x,
                            const float* __restrict__ embed_w) {
    int idx = blockIdx.x * blockDim.x + threadIdx.x;
    int nthreads = gridDim.x * blockDim.x;
    if (idx < NN*16) {
        int n = idx >> 4, t = idx & 15;
        float acc = 0.f;
#pragma unroll
        for (int k = 0; k < 8; k++) acc += x[n*8+k] * embed_w[k*16+t];
        g_s[idx] = acc * I8;
    }
    for (int i = idx; i < NN*24; i += nthreads) { g_v[i] = 0.f; g_aggs[i] = 0.f; }
    for (int i = idx; i < NN*96; i += nthreads) g_aggv[i] = 0.f;
}

// ---------------------------------------------------------------- fused message kernel (per layer)
__global__ void __launch_bounds__(256, 2)
msg_kernel(int l,
           const float* __restrict__ rw,   // [4][10][100]
           const float* __restrict__ rb,   // [4][100]
           const float* __restrict__ fcw,  // [4][100][704]
           const float* __restrict__ fcb,  // [4][704]
           const int* __restrict__ row,
           const int* __restrict__ col) {
    extern __shared__ float sm[];
    float* sh_h    = sm;                       // [100][32]
    float* sh_w    = sh_h    + RN*EB;          // [32][705]
    float* sh_sj   = sh_w    + EB*SWS;         // [32][16]
    float* sh_vj   = sh_sj   + EB*16;          // [32][24]
    float* sh_sh1  = sh_vj   + EB*24;          // [32][3]
    float* sh_vdot = sh_sh1  + EB*3;           // [32][8]
    float* sh_Mv   = sh_vdot + EB*8;           // [32][24]
    float* sh_rbf  = sh_Mv   + EB*24;          // [32][10]
    int*   sh_row  = (int*)(sh_rbf + EB*NB);   // [32]
    int*   sh_col  = sh_row + EB;              // [32]

    int tid = threadIdx.x;
    int e0  = blockIdx.x * EB;

    // ---- phase A: per-edge metadata (grid-stride: EB*NB = 320 > 256!)
    if (tid < EB)    { sh_row[tid] = row[e0+tid]; sh_col[tid] = col[e0+tid]; }
    if (tid < EB*3)  sh_sh1[tid] = g_sh1[e0*3 + tid];
    for (int i = tid; i < EB*NB; i += 256) sh_rbf[i] = g_rbf[e0*NB + i];
    __syncthreads();

    // ---- phase B: gather node features, compute h
    for (int i = tid; i < EB*16; i += 256) {
        int e = i >> 4, t = i & 15;
        sh_sj[i] = g_s[sh_row[e]*16 + t];
    }
    for (int i = tid; i < EB*24; i += 256) {
        int e = i / 24, t = i - e*24;
        sh_vj[i] = g_v[sh_row[e]*24 + t];
    }
    const float* rwl = rw + l*NB*RN;
    for (int i = tid; i < RN*EB; i += 256) {
        int r = i >> 5, e = i & 31;          // layout sh_h[r][e]
        float acc = rb[l*RN + r];
#pragma unroll
        for (int k = 0; k < NB; k++) acc += sh_rbf[e*NB + k] * rwl[k*RN + r];
        sh_h[i] = fmaxf(acc, 0.0f);
    }
    __syncthreads();

    // ---- phase B2: per-(edge,u) vdot and Mv  (256 items == 256 threads)
    {
        int e = tid >> 3, j = tid & 7;
        float s1x = sh_sh1[e*3+0], s1y = sh_sh1[e*3+1], s1z = sh_sh1[e*3+2];
        float ux = s1x*ISQ3, uy = s1y*ISQ3, uz = s1z*ISQ3;
        float vx = sh_vj[e*24 + j*3+0], vy = sh_vj[e*24 + j*3+1], vz = sh_vj[e*24 + j*3+2];
        float dot = ux*vx + uy*vy + uz*vz;
        sh_vdot[e*8 + j] = SQ3 * dot;                       // v . sh1
        sh_Mv[e*24 + j*3+0] = SQ75 * (dot*ux - vx*THIRD);   // (M v)_i
        sh_Mv[e*24 + j*3+1] = SQ75 * (dot*uy - vy*THIRD);
        sh_Mv[e*24 + j*3+2] = SQ75 * (dot*uz - vz*THIRD);
    }

    // ---- phase C: w = h @ fc_w + fc_b  (the 90-GFLOP stage)
    const float* fwl = fcw + l*RN*WN;
    const float* fbl = fcb + l*WN;
    for (int kb = 0; kb < WN; kb += 256) {
        int k = kb + tid;
        if (k < WN) {
            float acc[EB];
#pragma unroll
            for (int e = 0; e < EB; e++) acc[e] = 0.f;
            const float* fw = fwl + k;
#pragma unroll 4
            for (int r = 0; r < RN; r++) {
                float wv = fw[r*WN];
                const float4* h4 = (const float4*)(sh_h + r*EB);
#pragma unroll
                for (int q = 0; q < 8; q++) {
                    float4 hv = h4[q];
                    acc[q*4+0] += hv.x * wv;
                    acc[q*4+1] += hv.y * wv;
                    acc[q*4+2] += hv.z * wv;
                    acc[q*4+3] += hv.w * wv;
                }
            }
            float bias = fbl[k];
#pragma unroll
            for (int e = 0; e < EB; e++) sh_w[e*SWS + k] = acc[e] + bias;
        }
    }
    __syncthreads();

    // ---- phase D: messages + atomic scatter (8 threads per edge)
    {
        int e = tid >> 3, j = tid & 7;
        int c = sh_col[e];
        const float* we = sh_w + e*SWS;
        const float* sj = sh_sj + e*16;
        float s1x = sh_sh1[e*3+0], s1y = sh_sh1[e*3+1], s1z = sh_sh1[e*3+2];

        // m0 (0e) and m1 (t1 x sh1), two t-slots per thread
#pragma unroll
        for (int tt = 0; tt < 2; tt++) {
            int t = j + tt*8;
            float a0 = 0.f, a1 = 0.f;
#pragma unroll
            for (int u = 0; u < 16; u++) {
                float s = sj[u];
                a0 += we[u*16 + t] * s;
                a1 += we[256 + u*16 + t] * s;
            }
            atomicAdd(&g_aggs[c*24 + t], a0 * C_SC);
            float t1 = a1 * C_SC;
            atomicAdd(&g_aggv[c*96 + t*3 + 0], t1 * s1x);
            atomicAdd(&g_aggv[c*96 + t*3 + 1], t1 * s1y);
            atomicAdd(&g_aggv[c*96 + t*3 + 2], t1 * s1z);
        }
        // m2, m3, m4: one t-slot (j) per thread
        float a2x=0.f, a2y=0.f, a2z=0.f, a3=0.f, a4x=0.f, a4y=0.f, a4z=0.f;
#pragma unroll
        for (int u = 0; u < 8; u++) {
            float w2 = we[512 + u*8 + j];
            float w3 = we[576 + u*8 + j];
            float w4 = we[640 + u*8 + j];
            a2x += w2 * sh_vj[e*24 + u*3+0];
            a2y += w2 * sh_vj[e*24 + u*3+1];
            a2z += w2 * sh_vj[e*24 + u*3+2];
            a3  += w3 * sh_vdot[e*8 + u];
            a4x += w4 * sh_Mv[e*24 + u*3+0];
            a4y += w4 * sh_Mv[e*24 + u*3+1];
            a4z += w4 * sh_Mv[e*24 + u*3+2];
        }
        atomicAdd(&g_aggs[c*24 + 16 + j], a3 * C_CG);
        atomicAdd(&g_aggv[c*96 + (16+j)*3 + 0], a2x * C_V0);
        atomicAdd(&g_aggv[c*96 + (16+j)*3 + 1], a2y * C_V0);
        atomicAdd(&g_aggv[c*96 + (16+j)*3 + 2], a2z * C_V0);
        atomicAdd(&g_aggv[c*96 + (24+j)*3 + 0], a4x * C_CG);
        atomicAdd(&g_aggv[c*96 + (24+j)*3 + 1], a4y * C_CG);
        atomicAdd(&g_aggv[c*96 + (24+j)*3 + 2], a4z * C_CG);
    }
}

// ---------------------------------------------------------------- node update (per layer)
__global__ void update_kernel(int l,
                              const float* __restrict__ lws,  // [4][24][16]
                              const float* __restrict__ lwv)  // [4][32][8]
{
    __shared__ float s_lws[24*16];
    __shared__ float s_lwv[32*8];
    int tid = threadIdx.x;
    for (int i = tid; i < 384; i += blockDim.x) s_lws[i] = lws[l*384 + i];
    for (int i = tid; i < 256; i += blockDim.x) s_lwv[i] = lwv[l*256 + i];
    __syncthreads();
    int n = blockIdx.x * blockDim.x + tid;
    if (n >= NN) return;

    float aggs[24];
#pragma unroll
    for (int i = 0; i < 24; i++) { aggs[i] = g_aggs[n*24+i]; g_aggs[n*24+i] = 0.f; }
    float aggv[96];
#pragma unroll
    for (int i = 0; i < 96; i++) { aggv[i] = g_aggv[n*96+i]; g_aggv[n*96+i] = 0.f; }

#pragma unroll
    for (int t = 0; t < 16; t++) {
        float acc = 0.f;
#pragma unroll
        for (int u = 0; u < 24; u++) acc += aggs[u] * s_lws[u*16 + t];
        g_s[n*16 + t] += acc * I24;
    }
#pragma unroll
    for (int w = 0; w < 8; w++) {
        float ax = 0.f, ay = 0.f, az = 0.f;
#pragma unroll
        for (int u = 0; u < 32; u++) {
            float lw = s_lwv[u*8 + w];
            ax += aggv[u*3+0] * lw;
            ay += aggv[u*3+1] * lw;
            az += aggv[u*3+2] * lw;
        }
        g_v[n*24 + w*3+0] += ax * I32;
        g_v[n*24 + w*3+1] += ay * I32;
        g_v[n*24 + w*3+2] += az * I32;
    }
}

// ---------------------------------------------------------------- output
__global__ void out_kernel(const float* __restrict__ out_w, float* __restrict__ out) {
    int idx = blockIdx.x * blockDim.x + threadIdx.x;
    if (idx >= NN*8) return;
    int n = idx >> 3, t = idx & 7;
    float acc = 0.f;
#pragma unroll
    for (int k = 0; k < 16; k++) acc += g_s[n*16 + k] * out_w[k*8 + t];
    out[idx] = acc * I16;
}

// ---------------------------------------------------------------- launch
extern "C" void kernel_launch(void* const* d_in, const int* in_sizes, int n_in,
                              void* d_out, int out_size) {
    // Identify inputs by element count (robust to metadata ordering).
    // Unique sizes: x=80000, pos=30000, radial_w=4000, radial_b=400,
    // fc_w=281600, fc_b=2816, lin_ws=1536, lin_wv=1024, edge_index=320000.
    // embed_w and out_w are both 128: the FIRST 128 is embed_w, SECOND is out_w
    // (holds for both dict-insertion and alphabetical metadata orders).
    const float *x=0, *pos=0, *embed_w=0, *radial_w=0, *radial_b=0;
    const float *fc_w=0, *fc_b=0, *lin_ws=0, *lin_wv=0, *out_w=0;
    const int *ei=0;
    for (int i = 0; i < n_in; i++) {
        switch (in_sizes[i]) {
            case 80000:  x        = (const float*)d_in[i]; break;
            case 30000:  pos      = (const float*)d_in[i]; break;
            case 4000:   radial_w = (const float*)d_in[i]; break;
            case 400:    radial_b = (const float*)d_in[i]; break;
            case 281600: fc_w     = (const float*)d_in[i]; break;
            case 2816:   fc_b     = (const float*)d_in[i]; break;
            case 1536:   lin_ws   = (const float*)d_in[i]; break;
            case 1024:   lin_wv   = (const float*)d_in[i]; break;
            case 320000: ei       = (const int*)d_in[i]; break;
            case 128:
                if (!embed_w) embed_w = (const float*)d_in[i];
                else          out_w   = (const float*)d_in[i];
                break;
        }
    }
    const int* row = ei;
    const int* col = ei + NE;
    float* out = (float*)d_out;

    const int SMEM = (RN*EB + EB*SWS + EB*16 + EB*24 + EB*3 + EB*8 + EB*24 + EB*NB) * 4
                   + EB * 2 * 4;
    cudaFuncSetAttribute(msg_kernel, cudaFuncAttributeMaxDynamicSharedMemorySize, SMEM);

    geom_kernel<<<(NE + 255)/256, 256>>>(pos, row, col);
    init_kernel<<<(NN*16 + 255)/256, 256>>>(x, embed_w);

    for (int l = 0; l < 4; l++) {
        msg_kernel<<<NE/EB, 256, SMEM>>>(l, radial_w, radial_b, fc_w, fc_b, row, col);
        update_kernel<<<(NN + 127)/128, 128>>>(l, lin_ws, lin_wv);
    }
    out_kernel<<<(NN*8 + 255)/256, 256>>>(out_w, out);
}

// round 3
// speedup vs baseline: 1.0009x; 1.0009x over previous
#include <cuda_runtime.h>
#include <math.h>

#define NN 10000
#define NE 160000
#define NB 10
#define RN 100
#define WN 704
#define EB 32
#define SWS 705   /* padded shared stride for w tile */

#define SQ3   1.7320508075688772f
#define ISQ3  0.5773502691896258f
#define SQ75  2.7386127875258306f
#define C_SC  0.25f
#define C_V0  0.35355339059327373f
#define C_CG  0.20412414523193152f   /* 1/sqrt(24) */
#define I24   0.20412414523193152f
#define I32   0.17677669529663687f
#define I8    0.35355339059327373f
#define I16   0.25f
#define THIRD 0.3333333333333333f

__device__ float g_rbf[NE*NB];
__device__ float g_sh1[NE*3];
__device__ float g_s[NN*16];
__device__ float g_v[NN*24];
__device__ float g_aggs[NN*24];
__device__ float g_aggv[NN*96];

// ---------------------------------------------------------------- geometry
__global__ void geom_kernel(const float* __restrict__ pos,
                            const int* __restrict__ row,
                            const int* __restrict__ col) {
    int e = blockIdx.x * 256 + threadIdx.x;
    if (e >= NE) return;
    int r = row[e], c = col[e];
    float vx = pos[3*r+0] - pos[3*c+0];
    float vy = pos[3*r+1] - pos[3*c+1];
    float vz = pos[3*r+2] - pos[3*c+2];
    float len = sqrtf(vx*vx + vy*vy + vz*vz + 1e-12f);
    float inv = 1.0f / len;
    g_sh1[3*e+0] = SQ3 * vx * inv;
    g_sh1[3*e+1] = SQ3 * vy * inv;
    g_sh1[3*e+2] = SQ3 * vz * inv;
    const float step = 10.0f / 9.0f;
#pragma unroll
    for (int k = 0; k < NB; k++) {
        float d = len - (float)k * step;
        g_rbf[e*NB + k] = expf(-0.405f * d * d);   // coeff = -0.5/(10/9)^2 exactly
    }
}

// ---------------------------------------------------------------- init: s = x@embed/sqrt8, zero v/agg
__global__ void init_kernel(const float* __restrict__ x,
                            const float* __restrict__ embed_w) {
    int idx = blockIdx.x * blockDim.x + threadIdx.x;
    int nthreads = gridDim.x * blockDim.x;
    if (idx < NN*16) {
        int n = idx >> 4, t = idx & 15;
        float acc = 0.f;
#pragma unroll
        for (int k = 0; k < 8; k++) acc += x[n*8+k] * embed_w[k*16+t];
        g_s[idx] = acc * I8;
    }
    for (int i = idx; i < NN*24; i += nthreads) { g_v[i] = 0.f; g_aggs[i] = 0.f; }
    for (int i = idx; i < NN*96; i += nthreads) g_aggv[i] = 0.f;
}

// ---------------------------------------------------------------- fused message kernel (per layer)
__global__ void __launch_bounds__(256, 2)
msg_kernel(int l,
           const float* __restrict__ rw,   // [4][10][100]
           const float* __restrict__ rb,   // [4][100]
           const float* __restrict__ fcw,  // [4][100][704]
           const float* __restrict__ fcb,  // [4][704]
           const int* __restrict__ row,
           const int* __restrict__ col) {
    extern __shared__ float sm[];
    float* sh_h    = sm;                       // [100][32]
    float* sh_w    = sh_h    + RN*EB;          // [32][705]
    float* sh_sj   = sh_w    + EB*SWS;         // [32][16]
    float* sh_vj   = sh_sj   + EB*16;          // [32][24]
    float* sh_sh1  = sh_vj   + EB*24;          // [32][3]
    float* sh_vdot = sh_sh1  + EB*3;           // [32][8]
    float* sh_Mv   = sh_vdot + EB*8;           // [32][24]
    float* sh_rbf  = sh_Mv   + EB*24;          // [32][10]
    int*   sh_row  = (int*)(sh_rbf + EB*NB);   // [32]
    int*   sh_col  = sh_row + EB;              // [32]

    int tid = threadIdx.x;
    int e0  = blockIdx.x * EB;

    // ---- phase A: per-edge metadata (grid-stride: EB*NB = 320 > 256!)
    if (tid < EB)    { sh_row[tid] = row[e0+tid]; sh_col[tid] = col[e0+tid]; }
    if (tid < EB*3)  sh_sh1[tid] = g_sh1[e0*3 + tid];
    for (int i = tid; i < EB*NB; i += 256) sh_rbf[i] = g_rbf[e0*NB + i];
    __syncthreads();

    // ---- phase B: gather node features, compute h
    for (int i = tid; i < EB*16; i += 256) {
        int e = i >> 4, t = i & 15;
        sh_sj[i] = g_s[sh_row[e]*16 + t];
    }
    for (int i = tid; i < EB*24; i += 256) {
        int e = i / 24, t = i - e*24;
        sh_vj[i] = g_v[sh_row[e]*24 + t];
    }
    const float* rwl = rw + l*NB*RN;
    for (int i = tid; i < RN*EB; i += 256) {
        int r = i >> 5, e = i & 31;          // layout sh_h[r][e]
        float acc = rb[l*RN + r];
#pragma unroll
        for (int k = 0; k < NB; k++) acc += sh_rbf[e*NB + k] * rwl[k*RN + r];
        sh_h[i] = fmaxf(acc, 0.0f);
    }
    __syncthreads();

    // ---- phase B2: per-(edge,u) vdot and Mv  (256 items == 256 threads)
    {
        int e = tid >> 3, j = tid & 7;
        float s1x = sh_sh1[e*3+0], s1y = sh_sh1[e*3+1], s1z = sh_sh1[e*3+2];
        float ux = s1x*ISQ3, uy = s1y*ISQ3, uz = s1z*ISQ3;
        float vx = sh_vj[e*24 + j*3+0], vy = sh_vj[e*24 + j*3+1], vz = sh_vj[e*24 + j*3+2];
        float dot = ux*vx + uy*vy + uz*vz;
        sh_vdot[e*8 + j] = SQ3 * dot;                       // v . sh1
        sh_Mv[e*24 + j*3+0] = SQ75 * (dot*ux - vx*THIRD);   // (M v)_i
        sh_Mv[e*24 + j*3+1] = SQ75 * (dot*uy - vy*THIRD);
        sh_Mv[e*24 + j*3+2] = SQ75 * (dot*uz - vz*THIRD);
    }

    // ---- phase C: w = h @ fc_w + fc_b  (the 90-GFLOP stage)
    const float* fwl = fcw + l*RN*WN;
    const float* fbl = fcb + l*WN;
    for (int kb = 0; kb < WN; kb += 256) {
        int k = kb + tid;
        if (k < WN) {
            float acc[EB];
#pragma unroll
            for (int e = 0; e < EB; e++) acc[e] = 0.f;
            const float* fw = fwl + k;
#pragma unroll 4
            for (int r = 0; r < RN; r++) {
                float wv = fw[r*WN];
                const float4* h4 = (const float4*)(sh_h + r*EB);
#pragma unroll
                for (int q = 0; q < 8; q++) {
                    float4 hv = h4[q];
                    acc[q*4+0] += hv.x * wv;
                    acc[q*4+1] += hv.y * wv;
                    acc[q*4+2] += hv.z * wv;
                    acc[q*4+3] += hv.w * wv;
                }
            }
            float bias = fbl[k];
#pragma unroll
            for (int e = 0; e < EB; e++) sh_w[e*SWS + k] = acc[e] + bias;
        }
    }
    __syncthreads();

    // ---- phase D: messages + atomic scatter (8 threads per edge)
    {
        int e = tid >> 3, j = tid & 7;
        int c = sh_col[e];
        const float* we = sh_w + e*SWS;
        const float* sj = sh_sj + e*16;
        float s1x = sh_sh1[e*3+0], s1y = sh_sh1[e*3+1], s1z = sh_sh1[e*3+2];

        // m0 (0e) and m1 (t1 x sh1), two t-slots per thread
#pragma unroll
        for (int tt = 0; tt < 2; tt++) {
            int t = j + tt*8;
            float a0 = 0.f, a1 = 0.f;
#pragma unroll
            for (int u = 0; u < 16; u++) {
                float s = sj[u];
                a0 += we[u*16 + t] * s;
                a1 += we[256 + u*16 + t] * s;
            }
            atomicAdd(&g_aggs[c*24 + t], a0 * C_SC);
            float t1 = a1 * C_SC;
            atomicAdd(&g_aggv[c*96 + t*3 + 0], t1 * s1x);
            atomicAdd(&g_aggv[c*96 + t*3 + 1], t1 * s1y);
            atomicAdd(&g_aggv[c*96 + t*3 + 2], t1 * s1z);
        }
        // m2, m3, m4: one t-slot (j) per thread
        float a2x=0.f, a2y=0.f, a2z=0.f, a3=0.f, a4x=0.f, a4y=0.f, a4z=0.f;
#pragma unroll
        for (int u = 0; u < 8; u++) {
            float w2 = we[512 + u*8 + j];
            float w3 = we[576 + u*8 + j];
            float w4 = we[640 + u*8 + j];
            a2x += w2 * sh_vj[e*24 + u*3+0];
            a2y += w2 * sh_vj[e*24 + u*3+1];
            a2z += w2 * sh_vj[e*24 + u*3+2];
            a3  += w3 * sh_vdot[e*8 + u];
            a4x += w4 * sh_Mv[e*24 + u*3+0];
            a4y += w4 * sh_Mv[e*24 + u*3+1];
            a4z += w4 * sh_Mv[e*24 + u*3+2];
        }
        atomicAdd(&g_aggs[c*24 + 16 + j], a3 * C_CG);
        atomicAdd(&g_aggv[c*96 + (16+j)*3 + 0], a2x * C_V0);
        atomicAdd(&g_aggv[c*96 + (16+j)*3 + 1], a2y * C_V0);
        atomicAdd(&g_aggv[c*96 + (16+j)*3 + 2], a2z * C_V0);
        atomicAdd(&g_aggv[c*96 + (24+j)*3 + 0], a4x * C_CG);
        atomicAdd(&g_aggv[c*96 + (24+j)*3 + 1], a4y * C_CG);
        atomicAdd(&g_aggv[c*96 + (24+j)*3 + 2], a4z * C_CG);
    }
}

// ---------------------------------------------------------------- node update (per layer)
__global__ void update_kernel(int l,
                              const float* __restrict__ lws,  // [4][24][16]
                              const float* __restrict__ lwv)  // [4][32][8]
{
    __shared__ float s_lws[24*16];
    __shared__ float s_lwv[32*8];
    int tid = threadIdx.x;
    for (int i = tid; i < 384; i += blockDim.x) s_lws[i] = lws[l*384 + i];
    for (int i = tid; i < 256; i += blockDim.x) s_lwv[i] = lwv[l*256 + i];
    __syncthreads();
    int n = blockIdx.x * blockDim.x + tid;
    if (n >= NN) return;

    float aggs[24];
#pragma unroll
    for (int i = 0; i < 24; i++) { aggs[i] = g_aggs[n*24+i]; g_aggs[n*24+i] = 0.f; }
    float aggv[96];
#pragma unroll
    for (int i = 0; i < 96; i++) { aggv[i] = g_aggv[n*96+i]; g_aggv[n*96+i] = 0.f; }

#pragma unroll
    for (int t = 0; t < 16; t++) {
        float acc = 0.f;
#pragma unroll
        for (int u = 0; u < 24; u++) acc += aggs[u] * s_lws[u*16 + t];
        g_s[n*16 + t] += acc * I24;
    }
#pragma unroll
    for (int w = 0; w < 8; w++) {
        float ax = 0.f, ay = 0.f, az = 0.f;
#pragma unroll
        for (int u = 0; u < 32; u++) {
            float lw = s_lwv[u*8 + w];
            ax += aggv[u*3+0] * lw;
            ay += aggv[u*3+1] * lw;
            az += aggv[u*3+2] * lw;
        }
        g_v[n*24 + w*3+0] += ax * I32;
        g_v[n*24 + w*3+1] += ay * I32;
        g_v[n*24 + w*3+2] += az * I32;
    }
}

// ---------------------------------------------------------------- output
__global__ void out_kernel(const float* __restrict__ out_w, float* __restrict__ out) {
    int idx = blockIdx.x * blockDim.x + threadIdx.x;
    if (idx >= NN*8) return;
    int n = idx >> 3, t = idx & 7;
    float acc = 0.f;
#pragma unroll
    for (int k = 0; k < 16; k++) acc += g_s[n*16 + k] * out_w[k*8 + t];
    out[idx] = acc * I16;
}

// ---------------------------------------------------------------- launch
extern "C" void kernel_launch(void* const* d_in, const int* in_sizes, int n_in,
                              void* d_out, int out_size) {
    // Identify inputs by element count (robust to metadata ordering).
    // Unique sizes: x=80000, pos=30000, radial_w=4000, radial_b=400,
    // fc_w=281600, fc_b=2816, lin_ws=1536, lin_wv=1024, edge_index=320000.
    // embed_w and out_w are both 128: the FIRST 128 is embed_w, SECOND is out_w
    // (holds for both dict-insertion and alphabetical metadata orders).
    const float *x=0, *pos=0, *embed_w=0, *radial_w=0, *radial_b=0;
    const float *fc_w=0, *fc_b=0, *lin_ws=0, *lin_wv=0, *out_w=0;
    const int *ei=0;
    for (int i = 0; i < n_in; i++) {
        switch (in_sizes[i]) {
            case 80000:  x        = (const float*)d_in[i]; break;
            case 30000:  pos      = (const float*)d_in[i]; break;
            case 4000:   radial_w = (const float*)d_in[i]; break;
            case 400:    radial_b = (const float*)d_in[i]; break;
            case 281600: fc_w     = (const float*)d_in[i]; break;
            case 2816:   fc_b     = (const float*)d_in[i]; break;
            case 1536:   lin_ws   = (const float*)d_in[i]; break;
            case 1024:   lin_wv   = (const float*)d_in[i]; break;
            case 320000: ei       = (const int*)d_in[i]; break;
            case 128:
                if (!embed_w) embed_w = (const float*)d_in[i];
                else          out_w   = (const float*)d_in[i];
                break;
        }
    }
    const int* row = ei;
    const int* col = ei + NE;
    float* out = (float*)d_out;

    const int SMEM = (RN*EB + EB*SWS + EB*16 + EB*24 + EB*3 + EB*8 + EB*24 + EB*NB) * 4
                   + EB * 2 * 4;
    cudaFuncSetAttribute(msg_kernel, cudaFuncAttributeMaxDynamicSharedMemorySize, SMEM);

    geom_kernel<<<(NE + 255)/256, 256>>>(pos, row, col);
    init_kernel<<<(NN*16 + 255)/256, 256>>>(x, embed_w);

    for (int l = 0; l < 4; l++) {
        msg_kernel<<<NE/EB, 256, SMEM>>>(l, radial_w, radial_b, fc_w, fc_b, row, col);
        update_kernel<<<(NN + 127)/128, 128>>>(l, lin_ws, lin_wv);
    }
    out_kernel<<<(NN*8 + 255)/256, 256>>>(out_w, out);
}

// round 5
// speedup vs baseline: 2.0466x; 2.0448x over previous
#include <cuda_runtime.h>
#include <cuda_bf16.h>
#include <math.h>
#include <stdint.h>

#define NN 10000
#define NE 160000
#define NB 10
#define RN 100
#define WN 704
#define NCH 11
#define KP 112        /* padded K for mma (101 -> 112) */
#define KG 128        /* padded K in global BT (for x4 ldmatrix) */

#define SQ3    1.7320508075688772f
#define ISQ3   0.5773502691896258f
#define SQ75   2.7386127875258306f
#define C_SC   0.25f
#define C_V0   0.35355339059327373f
#define C_CG   0.20412414523193152f
#define I24    0.20412414523193152f
#define I32    0.17677669529663687f
#define I8     0.35355339059327373f
#define I16    0.25f
#define THIRD  0.3333333333333333f

__device__ float g_rbf[NE*NB];
__device__ float g_sh1[NE*3];
__device__ float g_s[NN*16];
__device__ float g_v[NN*24];
__device__ float g_aggs[NN*24];
__device__ float g_aggv[NN*96];
__device__ uint16_t g_bthi[4*WN*KG];   /* fc_w^T bf16 hi, [l][n][k] padded */
__device__ uint16_t g_btlo[4*WN*KG];   /* fc_w^T bf16 lo */

/* ---- dynamic smem layout (bytes) ----
   region U (0..57343): prologue = sh_hh[128*112]u16 | sh_hl[128*112]u16
                        chunk loop = w_buf[128*65]f32 (33280) + col[128]i32 (33792)
   FEAT (57344..96767): prologue = rwsm[1100]f32 ; later feat[128*77]f32 + pad
   BBUF (96768..162303): 2 bufs x 2 var x 16384                                  */
#define OFF_HH   0
#define OFF_HL   28672
#define OFF_WBUF 0
#define OFF_COL  33280
#define OFF_FEAT 57344
#define OFF_B    96768
#define SM_TOT   162304
#define FST 77

__device__ __forceinline__ uint32_t smem_u32(const void* p){
    uint32_t a; asm("{ .reg .u64 t; cvta.to.shared.u64 t, %1; cvt.u32.u64 %0, t; }":"=r"(a):"l"(p)); return a;
}
__device__ __forceinline__ void cpa16(uint32_t dst, const void* src){
    asm volatile("cp.async.ca.shared.global [%0], [%1], 16;"::"r"(dst),"l"(src):"memory");
}
__device__ __forceinline__ void cp_commit(){ asm volatile("cp.async.commit_group;":::"memory"); }
__device__ __forceinline__ void cp_wait0(){ asm volatile("cp.async.wait_group 0;":::"memory"); }
__device__ __forceinline__ void cp_wait1(){ asm volatile("cp.async.wait_group 1;":::"memory"); }
__device__ __forceinline__ void ldsm4(uint32_t* r, uint32_t a){
    asm volatile("ldmatrix.sync.aligned.m8n8.x4.shared.b16 {%0,%1,%2,%3}, [%4];"
        :"=r"(r[0]),"=r"(r[1]),"=r"(r[2]),"=r"(r[3]):"r"(a));
}
__device__ __forceinline__ void mma16816(float* d, const uint32_t* a, uint32_t b0, uint32_t b1){
    asm volatile("mma.sync.aligned.m16n8k16.row.col.f32.bf16.bf16.f32 "
        "{%0,%1,%2,%3}, {%4,%5,%6,%7}, {%8,%9}, {%0,%1,%2,%3};"
        : "+f"(d[0]),"+f"(d[1]),"+f"(d[2]),"+f"(d[3])
        : "r"(a[0]),"r"(a[1]),"r"(a[2]),"r"(a[3]),"r"(b0),"r"(b1));
}

/* ---------------- geometry ---------------- */
__global__ void geom_kernel(const float* __restrict__ pos, const int* __restrict__ row, const int* __restrict__ col){
    int e = blockIdx.x*256 + threadIdx.x;
    if (e >= NE) return;
    int r = row[e], c = col[e];
    float vx = pos[3*r]-pos[3*c], vy = pos[3*r+1]-pos[3*c+1], vz = pos[3*r+2]-pos[3*c+2];
    float len = sqrtf(vx*vx+vy*vy+vz*vz+1e-12f);
    float inv = 1.0f/len;
    g_sh1[3*e]=SQ3*vx*inv; g_sh1[3*e+1]=SQ3*vy*inv; g_sh1[3*e+2]=SQ3*vz*inv;
    const float step = 10.0f/9.0f;
#pragma unroll
    for (int k=0;k<NB;k++){ float d = len - (float)k*step; g_rbf[e*NB+k] = expf(-0.405f*d*d); }
}

/* ---------------- init ---------------- */
__global__ void init_kernel(const float* __restrict__ x, const float* __restrict__ ew){
    int idx = blockIdx.x*blockDim.x + threadIdx.x;
    int nt = gridDim.x*blockDim.x;
    if (idx < NN*16){
        int n = idx>>4, t = idx&15;
        float a = 0.f;
#pragma unroll
        for (int k=0;k<8;k++) a += x[n*8+k]*ew[k*16+t];
        g_s[idx] = a*I8;
    }
    for (int i=idx;i<NN*24;i+=nt){ g_v[i]=0.f; g_aggs[i]=0.f; }
    for (int i=idx;i<NN*96;i+=nt) g_aggv[i]=0.f;
}

/* ---------------- one-time fc_w -> BT bf16 hi/lo (padded K=128) ---------------- */
__global__ void conv_fcw(const float* __restrict__ fcw, const float* __restrict__ fcb){
    int idx = blockIdx.x*256 + threadIdx.x;
    if (idx >= 4*WN*KG) return;
    int k = idx & (KG-1);
    int n = (idx >> 7) % WN;
    int l = idx / (WN*KG);
    float v = 0.f;
    if (k < 100)       v = fcw[(size_t)(l*RN + k)*WN + n];
    else if (k == 100) v = fcb[l*WN + n];
    __nv_bfloat16 hi = __float2bfloat16(v);
    __nv_bfloat16 lo = __float2bfloat16(v - __bfloat162float(hi));
    g_bthi[idx] = *(uint16_t*)&hi;
    g_btlo[idx] = *(uint16_t*)&lo;
}

/* ---------------- fused HMMA message kernel ---------------- */
__global__ void __launch_bounds__(256, 1)
msg_kernel(int l, const int* __restrict__ row, const int* __restrict__ col,
           const float* __restrict__ rw, const float* __restrict__ rb){
    extern __shared__ char smem[];
    uint32_t sbase = smem_u32(smem);
    int tid = threadIdx.x;
    int wid = tid>>5, lane = tid&31;
    int g = lane>>2, tig = lane&3;
    int e0 = blockIdx.x*128;

    uint16_t* hh = (uint16_t*)(smem + OFF_HH);
    uint16_t* hl = (uint16_t*)(smem + OFF_HL);
    float*    wbuf = (float*)(smem + OFF_WBUF);
    int*      colsm = (int*)(smem + OFF_COL);
    float*    featf = (float*)(smem + OFF_FEAT);
    float*    rwsm  = featf;                     /* overlay during prologue */

    /* kick off B chunk 0 staging */
    {
        const uint16_t* srcs[2] = { g_bthi + (size_t)l*WN*KG, g_btlo + (size_t)l*WN*KG };
#pragma unroll
        for (int i=0;i<8;i++){
            int cid = tid + i*256;               /* 2048 16B chunks */
            int var = cid >> 10;
            int n   = (cid & 1023) >> 4;
            int j   = cid & 15;
            uint32_t dst = sbase + OFF_B + var*16384 + ((n*16 + (j ^ (n&7)))<<4);
            cpa16(dst, srcs[var] + ((size_t)n*KG + j*8));
        }
        cp_commit();
    }

    /* zero hh/hl, load radial weights */
    {
        uint32_t* z = (uint32_t*)(smem + OFF_HH);
        for (int i=tid;i<14336;i+=256) z[i] = 0;
        for (int i=tid;i<1100;i+=256) rwsm[i] = (i<1000) ? rw[l*1000+i] : rb[l*100+i-1000];
    }
    __syncthreads();

    /* h compute: thread = (edge, half), 50 r-values each, bf16 hi/lo */
    {
        int e = tid>>1, half = tid&1, eg = e0 + e;
        float rbf[NB];
#pragma unroll
        for (int k=0;k<NB;k++) rbf[k] = g_rbf[eg*NB+k];
        int r0 = half*50;
        for (int r=r0; r<r0+50; r++){
            float a = rwsm[1000+r];
#pragma unroll
            for (int k=0;k<NB;k++) a += rbf[k]*rwsm[k*RN+r];
            a = fmaxf(a, 0.f);
            __nv_bfloat16 bh = __float2bfloat16(a);
            __nv_bfloat16 bl = __float2bfloat16(a - __bfloat162float(bh));
            hh[e*KP + r] = *(uint16_t*)&bh;
            hl[e*KP + r] = *(uint16_t*)&bl;
        }
        if (half == 0) hh[e*KP + 100] = 0x3F80;   /* bias row: A = 1.0 */
    }
    __syncthreads();

    /* preload A fragments (hi & lo) into registers: rows wid*16+g / +8 */
    uint32_t ahh[28], ahl[28];
    {
        int ra = wid*16 + g;
#pragma unroll
        for (int ks=0;ks<7;ks++){
            int k0 = ks*16 + tig*2;
            ahh[ks*4+0] = *(uint32_t*)&hh[ra*KP + k0];
            ahh[ks*4+1] = *(uint32_t*)&hh[(ra+8)*KP + k0];
            ahh[ks*4+2] = *(uint32_t*)&hh[ra*KP + k0+8];
            ahh[ks*4+3] = *(uint32_t*)&hh[(ra+8)*KP + k0+8];
            ahl[ks*4+0] = *(uint32_t*)&hl[ra*KP + k0];
            ahl[ks*4+1] = *(uint32_t*)&hl[(ra+8)*KP + k0];
            ahl[ks*4+2] = *(uint32_t*)&hl[ra*KP + k0+8];
            ahl[ks*4+3] = *(uint32_t*)&hl[(ra+8)*KP + k0+8];
        }
    }
    __syncthreads();   /* done with hh/hl and rwsm; U & FEAT reusable */

    /* features + col (thread = edge, tid < 128) */
    if (tid < 128){
        int e = tid, eg = e0 + e;
        int rr = row[eg];
        colsm[e] = col[eg];
        float* F = featf + e*FST;
#pragma unroll
        for (int t=0;t<16;t++) F[t] = g_s[rr*16+t];
#pragma unroll
        for (int i=0;i<24;i++) F[16+i] = g_v[rr*24+i];
        float s1x = g_sh1[eg*3], s1y = g_sh1[eg*3+1], s1z = g_sh1[eg*3+2];
        F[72]=s1x; F[73]=s1y; F[74]=s1z;
        float ux=s1x*ISQ3, uy=s1y*ISQ3, uz=s1z*ISQ3;
#pragma unroll
        for (int u=0;u<8;u++){
            float vx=F[16+u*3], vy=F[17+u*3], vz=F[18+u*3];
            float dot = ux*vx+uy*vy+uz*vz;
            F[40+u] = SQ3*dot;
            F[48+u*3] = SQ75*(dot*ux - vx*THIRD);
            F[49+u*3] = SQ75*(dot*uy - vy*THIRD);
            F[50+u*3] = SQ75*(dot*uz - vz*THIRD);
        }
    }
    __syncthreads();

    /* chunk loop */
    int me = tid>>1, h8 = (tid&1)*8;
    const float* F = featf + me*FST;
    float s1x = F[72], s1y = F[73], s1z = F[74];
    float acc0[8], acc1[8];

    for (int c=0;c<NCH;c++){
        int bufc = c&1;
        /* prefetch chunk c+1 */
        if (c+1 < NCH){
            const uint16_t* srcs[2] = { g_bthi + (size_t)l*WN*KG + (size_t)(c+1)*64*KG,
                                        g_btlo + (size_t)l*WN*KG + (size_t)(c+1)*64*KG };
            uint32_t db = sbase + OFF_B + ((c+1)&1)*32768;
#pragma unroll
            for (int i=0;i<8;i++){
                int cid = tid + i*256;
                int var = cid >> 10;
                int n   = (cid & 1023) >> 4;
                int j   = cid & 15;
                cpa16(db + var*16384 + ((n*16 + (j ^ (n&7)))<<4),
                      srcs[var] + ((size_t)n*KG + j*8));
            }
            cp_commit();
            cp_wait1();
        } else {
            cp_wait0();
        }
        __syncthreads();

        /* GEMM: 8 n-frags x 7 k-steps x 3 passes */
        float accf[32];
#pragma unroll
        for (int i=0;i<32;i++) accf[i] = 0.f;
        {
            uint32_t bb = sbase + OFF_B + bufc*32768;
            int mi = lane>>3, rowin = lane&7;
#pragma unroll
            for (int q=0;q<4;q++){
#pragma unroll
                for (int nf=0;nf<8;nf++){
                    uint32_t off = ((nf*8 + rowin)*16 + ((q*4+mi) ^ rowin)) << 4;
                    uint32_t bh[4], bl[4];
                    ldsm4(bh, bb + off);
                    ldsm4(bl, bb + 16384 + off);
                    float* A = accf + nf*4;
                    mma16816(A, ahh + (2*q)*4, bh[0], bh[1]);
                    mma16816(A, ahh + (2*q)*4, bl[0], bl[1]);
                    mma16816(A, ahl + (2*q)*4, bh[0], bh[1]);
                    if (q < 3){
                        mma16816(A, ahh + (2*q+1)*4, bh[2], bh[3]);
                        mma16816(A, ahh + (2*q+1)*4, bl[2], bl[3]);
                        mma16816(A, ahl + (2*q+1)*4, bh[2], bh[3]);
                    }
                }
            }
        }
        /* store D -> w_buf [128][65] */
        {
            int r0 = wid*16 + g;
#pragma unroll
            for (int nf=0;nf<8;nf++){
                int cl = nf*8 + tig*2;
                wbuf[r0*65 + cl]     = accf[nf*4+0];
                wbuf[r0*65 + cl+1]   = accf[nf*4+1];
                wbuf[(r0+8)*65 + cl]   = accf[nf*4+2];
                wbuf[(r0+8)*65 + cl+1] = accf[nf*4+3];
            }
        }
        __syncthreads();

        /* messages: thread = (edge, half) */
        {
            int cn = colsm[me];
            const float* W = wbuf + me*65;
            if (c < 4){
                if (c == 0){
#pragma unroll
                    for (int t=0;t<8;t++) acc0[t] = 0.f;
                }
#pragma unroll
                for (int u=0;u<4;u++){
                    float s = F[c*4+u];
#pragma unroll
                    for (int t=0;t<8;t++) acc0[t] += W[u*16 + h8 + t]*s;
                }
                if (c == 3){
#pragma unroll
                    for (int t=0;t<8;t++) atomicAdd(&g_aggs[cn*24 + h8 + t], acc0[t]*C_SC);
                }
            } else if (c < 8){
                if (c == 4){
#pragma unroll
                    for (int t=0;t<8;t++) acc1[t] = 0.f;
                }
#pragma unroll
                for (int u=0;u<4;u++){
                    float s = F[(c-4)*4+u];
#pragma unroll
                    for (int t=0;t<8;t++) acc1[t] += W[u*16 + h8 + t]*s;
                }
                if (c == 7){
#pragma unroll
                    for (int t=0;t<8;t++){
                        float f = acc1[t]*C_SC;
                        int tg = h8 + t;
                        atomicAdd(&g_aggv[cn*96 + tg*3 + 0], f*s1x);
                        atomicAdd(&g_aggv[cn*96 + tg*3 + 1], f*s1y);
                        atomicAdd(&g_aggv[cn*96 + tg*3 + 2], f*s1z);
                    }
                }
            } else if (c == 8){
#pragma unroll
                for (int jj=0;jj<4;jj++){
                    int j = (h8>>1) + jj;     /* half*4 + jj */
                    float ax=0.f, ay=0.f, az=0.f;
#pragma unroll
                    for (int u=0;u<8;u++){
                        float w = W[u*8+j];
                        ax += w*F[16+u*3]; ay += w*F[17+u*3]; az += w*F[18+u*3];
                    }
                    atomicAdd(&g_aggv[cn*96 + (16+j)*3 + 0], ax*C_V0);
                    atomicAdd(&g_aggv[cn*96 + (16+j)*3 + 1], ay*C_V0);
                    atomicAdd(&g_aggv[cn*96 + (16+j)*3 + 2], az*C_V0);
                }
            } else if (c == 9){
#pragma unroll
                for (int jj=0;jj<4;jj++){
                    int j = (h8>>1) + jj;
                    float a = 0.f;
#pragma unroll
                    for (int u=0;u<8;u++) a += W[u*8+j]*F[40+u];
                    atomicAdd(&g_aggs[cn*24 + 16 + j], a*C_CG);
                }
            } else {
#pragma unroll
                for (int jj=0;jj<4;jj++){
                    int j = (h8>>1) + jj;
                    float ax=0.f, ay=0.f, az=0.f;
#pragma unroll
                    for (int u=0;u<8;u++){
                        float w = W[u*8+j];
                        ax += w*F[48+u*3]; ay += w*F[49+u*3]; az += w*F[50+u*3];
                    }
                    atomicAdd(&g_aggv[cn*96 + (24+j)*3 + 0], ax*C_CG);
                    atomicAdd(&g_aggv[cn*96 + (24+j)*3 + 1], ay*C_CG);
                    atomicAdd(&g_aggv[cn*96 + (24+j)*3 + 2], az*C_CG);
                }
            }
        }
        __syncthreads();
    }
}

/* ---------------- node updates ---------------- */
__global__ void upd_s(int l, const float* __restrict__ lws){
    int idx = blockIdx.x*256 + threadIdx.x;
    if (idx >= NN*16) return;
    int n = idx>>4, t = idx&15;
    float a = 0.f;
#pragma unroll
    for (int u=0;u<24;u++) a += g_aggs[n*24+u]*lws[l*384+u*16+t];
    g_s[idx] += a*I24;
}
__global__ void upd_v(int l, const float* __restrict__ lwv){
    int idx = blockIdx.x*256 + threadIdx.x;
    if (idx >= NN*8) return;
    int n = idx>>3, w = idx&7;
    float ax=0.f, ay=0.f, az=0.f;
#pragma unroll
    for (int u=0;u<32;u++){
        float lw = lwv[l*256+u*8+w];
        ax += g_aggv[n*96+u*3+0]*lw;
        ay += g_aggv[n*96+u*3+1]*lw;
        az += g_aggv[n*96+u*3+2]*lw;
    }
    g_v[n*24+w*3+0] += ax*I32;
    g_v[n*24+w*3+1] += ay*I32;
    g_v[n*24+w*3+2] += az*I32;
}
__global__ void zagg(){
    int i = blockIdx.x*256 + threadIdx.x;
    if (i < NN*24) g_aggs[i] = 0.f;
    if (i < NN*96) g_aggv[i] = 0.f;
}

/* ---------------- output ---------------- */
__global__ void out_kernel(const float* __restrict__ ow, float* __restrict__ out){
    int idx = blockIdx.x*256 + threadIdx.x;
    if (idx >= NN*8) return;
    int n = idx>>3, t = idx&7;
    float a = 0.f;
#pragma unroll
    for (int k=0;k<16;k++) a += g_s[n*16+k]*ow[k*8+t];
    out[idx] = a*I16;
}

/* ---------------- launch ---------------- */
extern "C" void kernel_launch(void* const* d_in, const int* in_sizes, int n_in,
                              void* d_out, int out_size){
    const float *x=0, *pos=0, *embed_w=0, *radial_w=0, *radial_b=0;
    const float *fc_w=0, *fc_b=0, *lin_ws=0, *lin_wv=0, *out_w=0;
    const int *ei=0;
    for (int i=0;i<n_in;i++){
        switch (in_sizes[i]){
            case 80000:  x=(const float*)d_in[i]; break;
            case 30000:  pos=(const float*)d_in[i]; break;
            case 4000:   radial_w=(const float*)d_in[i]; break;
            case 400:    radial_b=(const float*)d_in[i]; break;
            case 281600: fc_w=(const float*)d_in[i]; break;
            case 2816:   fc_b=(const float*)d_in[i]; break;
            case 1536:   lin_ws=(const float*)d_in[i]; break;
            case 1024:   lin_wv=(const float*)d_in[i]; break;
            case 320000: ei=(const int*)d_in[i]; break;
            case 128:
                if (!embed_w) embed_w=(const float*)d_in[i];
                else          out_w=(const float*)d_in[i];
                break;
        }
    }
    const int* row = ei;
    const int* col = ei + NE;
    float* out = (float*)d_out;

    cudaFuncSetAttribute(msg_kernel, cudaFuncAttributeMaxDynamicSharedMemorySize, SM_TOT);

    conv_fcw<<<(4*WN*KG + 255)/256, 256>>>(fc_w, fc_b);
    geom_kernel<<<(NE+255)/256, 256>>>(pos, row, col);
    init_kernel<<<(NN*16+255)/256, 256>>>(x, embed_w);

    for (int l=0;l<4;l++){
        msg_kernel<<<NE/128, 256, SM_TOT>>>(l, row, col, radial_w, radial_b);
        upd_s<<<(NN*16+255)/256, 256>>>(l, lin_ws);
        upd_v<<<(NN*8+255)/256, 256>>>(l, lin_wv);
        zagg<<<(NN*96+255)/256, 256>>>();
    }
    out_kernel<<<(NN*8+255)/256, 256>>>(out_w, out);
}

// round 6
// speedup vs baseline: 2.1688x; 1.0597x over previous
#include <cuda_runtime.h>
#include <cuda_bf16.h>
#include <math.h>
#include <stdint.h>

#define NN 10000
#define NE 160000
#define NB 10
#define RN 100
#define WN 704
#define NCH 11
#define EB 64         /* edges per CTA */
#define KP 112        /* padded K for mma (101 -> 112) */
#define KG 128        /* padded K in global BT (for x4 ldmatrix) */

#define SQ3    1.7320508075688772f
#define ISQ3   0.5773502691896258f
#define SQ75   2.7386127875258306f
#define C_SC   0.25f
#define C_V0   0.35355339059327373f
#define C_CG   0.20412414523193152f
#define I24    0.20412414523193152f
#define I32    0.17677669529663687f
#define I8     0.35355339059327373f
#define I16    0.25f
#define THIRD  0.3333333333333333f

__device__ float g_rbf[NE*NB];
__device__ float g_sh1[NE*3];
__device__ float g_s[NN*16];
__device__ float g_v[NN*24];
__device__ float g_aggs[NN*24];
__device__ float g_aggv[NN*96];
__device__ uint16_t g_bthi[4*WN*KG];   /* fc_w^T bf16 hi, [l][n][k] padded */
__device__ uint16_t g_btlo[4*WN*KG];   /* fc_w^T bf16 lo */

/* ---- dynamic smem layout (bytes), EB=64 ----
   region U (0..28671): prologue = hh[64*112]u16 | hl[64*112]u16
                        loop     = wbuf[64*65]f32 (16640) + col[64]i32
   FEAT (28672..48383): prologue = rwsm[1100]f32 ; later feat[64*77]f32
   BBUF (48384..113919): 2 bufs x 2 var x 16384                        */
#define OFF_HH   0
#define OFF_HL   14336
#define OFF_WBUF 0
#define OFF_COL  16640
#define OFF_FEAT 28672
#define OFF_B    48384
#define SM_TOT   113920
#define FST 77

__device__ __forceinline__ uint32_t smem_u32(const void* p){
    uint32_t a; asm("{ .reg .u64 t; cvta.to.shared.u64 t, %1; cvt.u32.u64 %0, t; }":"=r"(a):"l"(p)); return a;
}
__device__ __forceinline__ void cpa16(uint32_t dst, const void* src){
    asm volatile("cp.async.ca.shared.global [%0], [%1], 16;"::"r"(dst),"l"(src):"memory");
}
__device__ __forceinline__ void cp_commit(){ asm volatile("cp.async.commit_group;":::"memory"); }
__device__ __forceinline__ void cp_wait0(){ asm volatile("cp.async.wait_group 0;":::"memory"); }
__device__ __forceinline__ void cp_wait1(){ asm volatile("cp.async.wait_group 1;":::"memory"); }
__device__ __forceinline__ void ldsm4(uint32_t* r, uint32_t a){
    asm volatile("ldmatrix.sync.aligned.m8n8.x4.shared.b16 {%0,%1,%2,%3}, [%4];"
        :"=r"(r[0]),"=r"(r[1]),"=r"(r[2]),"=r"(r[3]):"r"(a));
}
__device__ __forceinline__ void mma16816(float* d, const uint32_t* a, uint32_t b0, uint32_t b1){
    asm volatile("mma.sync.aligned.m16n8k16.row.col.f32.bf16.bf16.f32 "
        "{%0,%1,%2,%3}, {%4,%5,%6,%7}, {%8,%9}, {%0,%1,%2,%3};"
        : "+f"(d[0]),"+f"(d[1]),"+f"(d[2]),"+f"(d[3])
        : "r"(a[0]),"r"(a[1]),"r"(a[2]),"r"(a[3]),"r"(b0),"r"(b1));
}

/* ---------------- geometry ---------------- */
__global__ void geom_kernel(const float* __restrict__ pos, const int* __restrict__ row, const int* __restrict__ col){
    int e = blockIdx.x*256 + threadIdx.x;
    if (e >= NE) return;
    int r = row[e], c = col[e];
    float vx = pos[3*r]-pos[3*c], vy = pos[3*r+1]-pos[3*c+1], vz = pos[3*r+2]-pos[3*c+2];
    float len = sqrtf(vx*vx+vy*vy+vz*vz+1e-12f);
    float inv = 1.0f/len;
    g_sh1[3*e]=SQ3*vx*inv; g_sh1[3*e+1]=SQ3*vy*inv; g_sh1[3*e+2]=SQ3*vz*inv;
    const float step = 10.0f/9.0f;
#pragma unroll
    for (int k=0;k<NB;k++){ float d = len - (float)k*step; g_rbf[e*NB+k] = expf(-0.405f*d*d); }
}

/* ---------------- init ---------------- */
__global__ void init_kernel(const float* __restrict__ x, const float* __restrict__ ew){
    int idx = blockIdx.x*blockDim.x + threadIdx.x;
    int nt = gridDim.x*blockDim.x;
    if (idx < NN*16){
        int n = idx>>4, t = idx&15;
        float a = 0.f;
#pragma unroll
        for (int k=0;k<8;k++) a += x[n*8+k]*ew[k*16+t];
        g_s[idx] = a*I8;
    }
    for (int i=idx;i<NN*24;i+=nt){ g_v[i]=0.f; g_aggs[i]=0.f; }
    for (int i=idx;i<NN*96;i+=nt) g_aggv[i]=0.f;
}

/* ---------------- one-time fc_w -> BT bf16 hi/lo (padded K=128) ---------------- */
__global__ void conv_fcw(const float* __restrict__ fcw, const float* __restrict__ fcb){
    int idx = blockIdx.x*256 + threadIdx.x;
    if (idx >= 4*WN*KG) return;
    int k = idx & (KG-1);
    int n = (idx >> 7) % WN;
    int l = idx / (WN*KG);
    float v = 0.f;
    if (k < 100)       v = fcw[(size_t)(l*RN + k)*WN + n];
    else if (k == 100) v = fcb[l*WN + n];
    __nv_bfloat16 hi = __float2bfloat16(v);
    __nv_bfloat16 lo = __float2bfloat16(v - __bfloat162float(hi));
    g_bthi[idx] = *(uint16_t*)&hi;
    g_btlo[idx] = *(uint16_t*)&lo;
}

/* ---------------- fused HMMA message kernel (64-edge tiles, 2 CTA/SM) ---------------- */
__global__ void __launch_bounds__(256, 2)
msg_kernel(int l, const int* __restrict__ row, const int* __restrict__ col,
           const float* __restrict__ rw, const float* __restrict__ rb){
    extern __shared__ char smem[];
    uint32_t sbase = smem_u32(smem);
    int tid = threadIdx.x;
    int wid = tid>>5, lane = tid&31;
    int g = lane>>2, tig = lane&3;
    int e0 = blockIdx.x*EB;

    uint16_t* hh = (uint16_t*)(smem + OFF_HH);
    uint16_t* hl = (uint16_t*)(smem + OFF_HL);
    float*    wbuf = (float*)(smem + OFF_WBUF);
    int*      colsm = (int*)(smem + OFF_COL);
    float*    featf = (float*)(smem + OFF_FEAT);
    float*    rwsm  = featf;                     /* overlay during prologue */

    /* kick off B chunk 0 staging (hi+lo = 2048 16B transfers) */
    {
        const uint16_t* srcs[2] = { g_bthi + (size_t)l*WN*KG, g_btlo + (size_t)l*WN*KG };
#pragma unroll
        for (int i=0;i<8;i++){
            int cid = tid + i*256;
            int var = cid >> 10;
            int n   = (cid & 1023) >> 4;
            int j   = cid & 15;
            uint32_t dst = sbase + OFF_B + var*16384 + ((n*16 + (j ^ (n&7)))<<4);
            cpa16(dst, srcs[var] + ((size_t)n*KG + j*8));
        }
        cp_commit();
    }

    /* zero hh/hl, load radial weights */
    {
        uint32_t* z = (uint32_t*)(smem + OFF_HH);
        for (int i=tid;i<7168;i+=256) z[i] = 0;
        for (int i=tid;i<1100;i+=256) rwsm[i] = (i<1000) ? rw[l*1000+i] : rb[l*100+i-1000];
    }
    __syncthreads();

    /* h compute: thread = (edge, quarter), 25 r-values each, bf16 hi/lo */
    {
        int e = tid>>2, q = tid&3, eg = e0 + e;
        float rbf[NB];
#pragma unroll
        for (int k=0;k<NB;k++) rbf[k] = g_rbf[eg*NB+k];
        int r0 = q*25;
        for (int r=r0; r<r0+25; r++){
            float a = rwsm[1000+r];
#pragma unroll
            for (int k=0;k<NB;k++) a += rbf[k]*rwsm[k*RN+r];
            a = fmaxf(a, 0.f);
            __nv_bfloat16 bh = __float2bfloat16(a);
            __nv_bfloat16 bl = __float2bfloat16(a - __bfloat162float(bh));
            hh[e*KP + r] = *(uint16_t*)&bh;
            hl[e*KP + r] = *(uint16_t*)&bl;
        }
        if (q == 0) hh[e*KP + 100] = 0x3F80;   /* bias row: A = 1.0 */
    }
    __syncthreads();

    /* preload A fragments: strip = wid&3 -> rows (wid&3)*16+g / +8 */
    uint32_t ahh[28], ahl[28];
    {
        int ra = (wid&3)*16 + g;
#pragma unroll
        for (int ks=0;ks<7;ks++){
            int k0 = ks*16 + tig*2;
            ahh[ks*4+0] = *(uint32_t*)&hh[ra*KP + k0];
            ahh[ks*4+1] = *(uint32_t*)&hh[(ra+8)*KP + k0];
            ahh[ks*4+2] = *(uint32_t*)&hh[ra*KP + k0+8];
            ahh[ks*4+3] = *(uint32_t*)&hh[(ra+8)*KP + k0+8];
            ahl[ks*4+0] = *(uint32_t*)&hl[ra*KP + k0];
            ahl[ks*4+1] = *(uint32_t*)&hl[(ra+8)*KP + k0];
            ahl[ks*4+2] = *(uint32_t*)&hl[ra*KP + k0+8];
            ahl[ks*4+3] = *(uint32_t*)&hl[(ra+8)*KP + k0+8];
        }
    }
    __syncthreads();   /* done with hh/hl and rwsm */

    /* features + col (thread = edge, tid < 64) */
    if (tid < EB){
        int e = tid, eg = e0 + e;
        int rr = row[eg];
        colsm[e] = col[eg];
        float* F = featf + e*FST;
#pragma unroll
        for (int t=0;t<16;t++) F[t] = g_s[rr*16+t];
#pragma unroll
        for (int i=0;i<24;i++) F[16+i] = g_v[rr*24+i];
        float s1x = g_sh1[eg*3], s1y = g_sh1[eg*3+1], s1z = g_sh1[eg*3+2];
        F[72]=s1x; F[73]=s1y; F[74]=s1z;
        float ux=s1x*ISQ3, uy=s1y*ISQ3, uz=s1z*ISQ3;
#pragma unroll
        for (int u=0;u<8;u++){
            float vx=F[16+u*3], vy=F[17+u*3], vz=F[18+u*3];
            float dot = ux*vx+uy*vy+uz*vz;
            F[40+u] = SQ3*dot;
            F[48+u*3] = SQ75*(dot*ux - vx*THIRD);
            F[49+u*3] = SQ75*(dot*uy - vy*THIRD);
            F[50+u*3] = SQ75*(dot*uz - vz*THIRD);
        }
    }
    __syncthreads();

    /* chunk loop: thread = (edge me, quarter mq) for messages */
    int me = tid>>2, mq = tid&3;
    const float* F = featf + me*FST;
    float s1x = F[72], s1y = F[73], s1z = F[74];
    int cn = colsm[me];
    int nfbase = (wid>>2)*4;
    float acc0[4], acc1[4];

    for (int c=0;c<NCH;c++){
        int bufc = c&1;
        /* prefetch chunk c+1 */
        if (c+1 < NCH){
            const uint16_t* srcs[2] = { g_bthi + (size_t)l*WN*KG + (size_t)(c+1)*64*KG,
                                        g_btlo + (size_t)l*WN*KG + (size_t)(c+1)*64*KG };
            uint32_t db = sbase + OFF_B + ((c+1)&1)*32768;
#pragma unroll
            for (int i=0;i<8;i++){
                int cid = tid + i*256;
                int var = cid >> 10;
                int n   = (cid & 1023) >> 4;
                int j   = cid & 15;
                cpa16(db + var*16384 + ((n*16 + (j ^ (n&7)))<<4),
                      srcs[var] + ((size_t)n*KG + j*8));
            }
            cp_commit();
            cp_wait1();
        } else {
            cp_wait0();
        }
        __syncthreads();

        /* GEMM: 4 local n-frags x 7 k-steps x 3 passes */
        float accf[16];
#pragma unroll
        for (int i=0;i<16;i++) accf[i] = 0.f;
        {
            uint32_t bb = sbase + OFF_B + bufc*32768;
            int mi = lane>>3, rowin = lane&7;
#pragma unroll
            for (int q4=0;q4<4;q4++){
#pragma unroll
                for (int nf=0;nf<4;nf++){
                    int nfg = nfbase + nf;
                    uint32_t off = ((nfg*8 + rowin)*16 + ((q4*4+mi) ^ rowin)) << 4;
                    uint32_t bh[4], bl[4];
                    ldsm4(bh, bb + off);
                    ldsm4(bl, bb + 16384 + off);
                    float* A = accf + nf*4;
                    mma16816(A, ahh + (2*q4)*4, bh[0], bh[1]);
                    mma16816(A, ahh + (2*q4)*4, bl[0], bl[1]);
                    mma16816(A, ahl + (2*q4)*4, bh[0], bh[1]);
                    if (q4 < 3){
                        mma16816(A, ahh + (2*q4+1)*4, bh[2], bh[3]);
                        mma16816(A, ahh + (2*q4+1)*4, bl[2], bl[3]);
                        mma16816(A, ahl + (2*q4+1)*4, bh[2], bh[3]);
                    }
                }
            }
        }
        /* store D -> w_buf [64][65] */
        {
            int r0 = (wid&3)*16 + g;
#pragma unroll
            for (int nf=0;nf<4;nf++){
                int cl = (nfbase+nf)*8 + tig*2;
                wbuf[r0*65 + cl]       = accf[nf*4+0];
                wbuf[r0*65 + cl+1]     = accf[nf*4+1];
                wbuf[(r0+8)*65 + cl]   = accf[nf*4+2];
                wbuf[(r0+8)*65 + cl+1] = accf[nf*4+3];
            }
        }
        __syncthreads();

        /* messages: thread = (edge, quarter) */
        {
            const float* W = wbuf + me*65;
            if (c < 4){
                if (c == 0){
#pragma unroll
                    for (int t=0;t<4;t++) acc0[t] = 0.f;
                }
#pragma unroll
                for (int u=0;u<4;u++){
                    float s = F[c*4+u];
#pragma unroll
                    for (int t=0;t<4;t++) acc0[t] += W[u*16 + mq*4 + t]*s;
                }
                if (c == 3){
#pragma unroll
                    for (int t=0;t<4;t++) atomicAdd(&g_aggs[cn*24 + mq*4 + t], acc0[t]*C_SC);
                }
            } else if (c < 8){
                if (c == 4){
#pragma unroll
                    for (int t=0;t<4;t++) acc1[t] = 0.f;
                }
#pragma unroll
                for (int u=0;u<4;u++){
                    float s = F[(c-4)*4+u];
#pragma unroll
                    for (int t=0;t<4;t++) acc1[t] += W[u*16 + mq*4 + t]*s;
                }
                if (c == 7){
#pragma unroll
                    for (int t=0;t<4;t++){
                        float f = acc1[t]*C_SC;
                        int tg = mq*4 + t;
                        atomicAdd(&g_aggv[cn*96 + tg*3 + 0], f*s1x);
                        atomicAdd(&g_aggv[cn*96 + tg*3 + 1], f*s1y);
                        atomicAdd(&g_aggv[cn*96 + tg*3 + 2], f*s1z);
                    }
                }
            } else if (c == 8){
#pragma unroll
                for (int jj=0;jj<2;jj++){
                    int j = mq*2 + jj;
                    float ax=0.f, ay=0.f, az=0.f;
#pragma unroll
                    for (int u=0;u<8;u++){
                        float w = W[u*8+j];
                        ax += w*F[16+u*3]; ay += w*F[17+u*3]; az += w*F[18+u*3];
                    }
                    atomicAdd(&g_aggv[cn*96 + (16+j)*3 + 0], ax*C_V0);
                    atomicAdd(&g_aggv[cn*96 + (16+j)*3 + 1], ay*C_V0);
                    atomicAdd(&g_aggv[cn*96 + (16+j)*3 + 2], az*C_V0);
                }
            } else if (c == 9){
#pragma unroll
                for (int jj=0;jj<2;jj++){
                    int j = mq*2 + jj;
                    float a = 0.f;
#pragma unroll
                    for (int u=0;u<8;u++) a += W[u*8+j]*F[40+u];
                    atomicAdd(&g_aggs[cn*24 + 16 + j], a*C_CG);
                }
            } else {
#pragma unroll
                for (int jj=0;jj<2;jj++){
                    int j = mq*2 + jj;
                    float ax=0.f, ay=0.f, az=0.f;
#pragma unroll
                    for (int u=0;u<8;u++){
                        float w = W[u*8+j];
                        ax += w*F[48+u*3]; ay += w*F[49+u*3]; az += w*F[50+u*3];
                    }
                    atomicAdd(&g_aggv[cn*96 + (24+j)*3 + 0], ax*C_CG);
                    atomicAdd(&g_aggv[cn*96 + (24+j)*3 + 1], ay*C_CG);
                    atomicAdd(&g_aggv[cn*96 + (24+j)*3 + 2], az*C_CG);
                }
            }
        }
        __syncthreads();
    }
}

/* ---------------- node updates ---------------- */
__global__ void upd_s(int l, const float* __restrict__ lws){
    int idx = blockIdx.x*256 + threadIdx.x;
    if (idx >= NN*16) return;
    int n = idx>>4, t = idx&15;
    float a = 0.f;
#pragma unroll
    for (int u=0;u<24;u++) a += g_aggs[n*24+u]*lws[l*384+u*16+t];
    g_s[idx] += a*I24;
}
__global__ void upd_v(int l, const float* __restrict__ lwv){
    int idx = blockIdx.x*256 + threadIdx.x;
    if (idx >= NN*8) return;
    int n = idx>>3, w = idx&7;
    float ax=0.f, ay=0.f, az=0.f;
#pragma unroll
    for (int u=0;u<32;u++){
        float lw = lwv[l*256+u*8+w];
        ax += g_aggv[n*96+u*3+0]*lw;
        ay += g_aggv[n*96+u*3+1]*lw;
        az += g_aggv[n*96+u*3+2]*lw;
    }
    g_v[n*24+w*3+0] += ax*I32;
    g_v[n*24+w*3+1] += ay*I32;
    g_v[n*24+w*3+2] += az*I32;
}
__global__ void zagg(){
    int i = blockIdx.x*256 + threadIdx.x;
    if (i < NN*24) g_aggs[i] = 0.f;
    if (i < NN*96) g_aggv[i] = 0.f;
}

/* ---------------- output ---------------- */
__global__ void out_kernel(const float* __restrict__ ow, float* __restrict__ out){
    int idx = blockIdx.x*256 + threadIdx.x;
    if (idx >= NN*8) return;
    int n = idx>>3, t = idx&7;
    float a = 0.f;
#pragma unroll
    for (int k=0;k<16;k++) a += g_s[n*16+k]*ow[k*8+t];
    out[idx] = a*I16;
}

/* ---------------- launch ---------------- */
extern "C" void kernel_launch(void* const* d_in, const int* in_sizes, int n_in,
                              void* d_out, int out_size){
    const float *x=0, *pos=0, *embed_w=0, *radial_w=0, *radial_b=0;
    const float *fc_w=0, *fc_b=0, *lin_ws=0, *lin_wv=0, *out_w=0;
    const int *ei=0;
    for (int i=0;i<n_in;i++){
        switch (in_sizes[i]){
            case 80000:  x=(const float*)d_in[i]; break;
            case 30000:  pos=(const float*)d_in[i]; break;
            case 4000:   radial_w=(const float*)d_in[i]; break;
            case 400:    radial_b=(const float*)d_in[i]; break;
            case 281600: fc_w=(const float*)d_in[i]; break;
            case 2816:   fc_b=(const float*)d_in[i]; break;
            case 1536:   lin_ws=(const float*)d_in[i]; break;
            case 1024:   lin_wv=(const float*)d_in[i]; break;
            case 320000: ei=(const int*)d_in[i]; break;
            case 128:
                if (!embed_w) embed_w=(const float*)d_in[i];
                else          out_w=(const float*)d_in[i];
                break;
        }
    }
    const int* row = ei;
    const int* col = ei + NE;
    float* out = (float*)d_out;

    cudaFuncSetAttribute(msg_kernel, cudaFuncAttributeMaxDynamicSharedMemorySize, SM_TOT);

    conv_fcw<<<(4*WN*KG + 255)/256, 256>>>(fc_w, fc_b);
    geom_kernel<<<(NE+255)/256, 256>>>(pos, row, col);
    init_kernel<<<(NN*16+255)/256, 256>>>(x, embed_w);

    for (int l=0;l<4;l++){
        msg_kernel<<<NE/EB, 256, SM_TOT>>>(l, row, col, radial_w, radial_b);
        upd_s<<<(NN*16+255)/256, 256>>>(l, lin_ws);
        upd_v<<<(NN*8+255)/256, 256>>>(l, lin_wv);
        zagg<<<(NN*96+255)/256, 256>>>();
    }
    out_kernel<<<(NN*8+255)/256, 256>>>(out_w, out);
}